// round 2
// baseline (speedup 1.0000x reference)
#include <cuda_runtime.h>
#include <cstdint>

typedef unsigned long long ull;

// ---- packed f32x2 helpers (sm_103a) ----
__device__ __forceinline__ ull ffma2(ull a, ull b, ull c) {
    ull d;
    asm("fma.rn.f32x2 %0, %1, %2, %3;" : "=l"(d) : "l"(a), "l"(b), "l"(c));
    return d;
}
__device__ __forceinline__ ull fmul2(ull a, ull b) {
    ull d;
    asm("mul.rn.f32x2 %0, %1, %2;" : "=l"(d) : "l"(a), "l"(b));
    return d;
}
__device__ __forceinline__ ull fadd2(ull a, ull b) {
    ull d;
    asm("add.rn.f32x2 %0, %1, %2;" : "=l"(d) : "l"(a), "l"(b));
    return d;
}
__device__ __forceinline__ ull pack2(float lo, float hi) {
    ull d;
    asm("mov.b64 %0, {%1, %2};" : "=l"(d) : "f"(lo), "f"(hi));
    return d;
}
__device__ __forceinline__ ull dup2(float v) { return pack2(v, v); }
__device__ __forceinline__ float2 unpack2(ull v) {
    float lo, hi;
    asm("mov.b64 {%0, %1}, %2;" : "=f"(lo), "=f"(hi) : "l"(v));
    return make_float2(lo, hi);
}

constexpr int D_DIM       = 1024;
constexpr int THREADS     = 256;
constexpr int ROWS_PER_BLK = 64;
constexpr int BATCH       = 16;
constexpr int PART_STRIDE = 49;   // 48 used slots (16 rows * 3 pairs) + 1 pad, in ull

__global__ void __launch_bounds__(THREADS)
q6_kernel(const float* __restrict__ x,
          const float* __restrict__ W,
          const float* __restrict__ proto,
          const float* __restrict__ hs,
          float* __restrict__ out)
{
    // partials: [g=0..63][row*3+pair], padded stride to kill bank conflicts
    __shared__ ull   part[64 * PART_STRIDE];
    __shared__ ull   zz[BATCH * 3];
    __shared__ float pn[8][6];
    __shared__ float s3_sh;

    const int tid  = threadIdx.x;
    const int lane = tid & 31;
    const int warp = tid >> 5;
    const int col  = tid * 4;        // this thread owns columns [col, col+4)

    // ---- one-time block init: normalized prototypes + fused scale ----
    if (tid < 8) {
        float v[6]; float ss = 0.f;
        #pragma unroll
        for (int k = 0; k < 6; ++k) { v[k] = proto[tid * 6 + k]; ss += v[k] * v[k]; }
        float n = fmaxf(sqrtf(ss), 1e-12f);
        #pragma unroll
        for (int k = 0; k < 6; ++k) pn[tid][k] = v[k] / n;
    }
    if (tid == 8) s3_sh = 3.0f * hs[0];   // softmax(-hs*(6-6d)/2) == softmax(3*hs*d)

    // ---- W slice for this thread's 4 columns, packed (k0,k1),(k2,k3),(k4,k5) ----
    ull wp[4][3];
    {
        float4 w4[6];
        #pragma unroll
        for (int k = 0; k < 6; ++k)
            w4[k] = *reinterpret_cast<const float4*>(W + k * D_DIM + col);
        #pragma unroll
        for (int p = 0; p < 3; ++p) {
            wp[0][p] = pack2(w4[2*p].x, w4[2*p+1].x);
            wp[1][p] = pack2(w4[2*p].y, w4[2*p+1].y);
            wp[2][p] = pack2(w4[2*p].z, w4[2*p+1].z);
            wp[3][p] = pack2(w4[2*p].w, w4[2*p+1].w);
        }
    }

    const int rowbase = blockIdx.x * ROWS_PER_BLK;

    for (int b = 0; b < ROWS_PER_BLK / BATCH; ++b) {
        const int    r0 = rowbase + b * BATCH;
        const float* xp = x + (size_t)r0 * D_DIM + col;

        // ---------------- phase 1: partial dots + 2-round butterfly ----------------
        #pragma unroll
        for (int r = 0; r < BATCH; r += 4) {
            float4 xv[4];
            #pragma unroll
            for (int u = 0; u < 4; ++u)   // batch 4 streaming loads -> MLP=4
                xv[u] = __ldcs(reinterpret_cast<const float4*>(xp + (size_t)(r + u) * D_DIM));
            #pragma unroll
            for (int u = 0; u < 4; ++u) {
                ull xx = dup2(xv[u].x);
                ull a0 = fmul2(xx, wp[0][0]);
                ull a1 = fmul2(xx, wp[0][1]);
                ull a2 = fmul2(xx, wp[0][2]);
                xx = dup2(xv[u].y);
                a0 = ffma2(xx, wp[1][0], a0);
                a1 = ffma2(xx, wp[1][1], a1);
                a2 = ffma2(xx, wp[1][2], a2);
                xx = dup2(xv[u].z);
                a0 = ffma2(xx, wp[2][0], a0);
                a1 = ffma2(xx, wp[2][1], a1);
                a2 = ffma2(xx, wp[2][2], a2);
                xx = dup2(xv[u].w);
                a0 = ffma2(xx, wp[3][0], a0);
                a1 = ffma2(xx, wp[3][1], a1);
                a2 = ffma2(xx, wp[3][2], a2);

                // reduce lanes {l, l^1} then {l, l^2}: lane%4==0 holds group-of-4 sum
                a0 = fadd2(a0, __shfl_xor_sync(0xffffffffu, a0, 1));
                a1 = fadd2(a1, __shfl_xor_sync(0xffffffffu, a1, 1));
                a2 = fadd2(a2, __shfl_xor_sync(0xffffffffu, a2, 1));
                a0 = fadd2(a0, __shfl_xor_sync(0xffffffffu, a0, 2));
                a1 = fadd2(a1, __shfl_xor_sync(0xffffffffu, a1, 2));
                a2 = fadd2(a2, __shfl_xor_sync(0xffffffffu, a2, 2));

                if ((lane & 3) == 0) {
                    const int g = warp * 8 + (lane >> 2);   // 0..63
                    ull* dst = part + g * PART_STRIDE + (r + u) * 3;
                    dst[0] = a0; dst[1] = a1; dst[2] = a2;
                }
            }
        }
        __syncthreads();

        // ---------------- phase 2: sum the 64 group partials per (row, pair) ------
        if (tid < BATCH * 3) {
            ull s0 = 0ull, s1 = 0ull, s2 = 0ull, s3v = 0ull;
            #pragma unroll
            for (int g = 0; g < 64; g += 4) {
                s0  = fadd2(s0,  part[(g + 0) * PART_STRIDE + tid]);
                s1  = fadd2(s1,  part[(g + 1) * PART_STRIDE + tid]);
                s2  = fadd2(s2,  part[(g + 2) * PART_STRIDE + tid]);
                s3v = fadd2(s3v, part[(g + 3) * PART_STRIDE + tid]);
            }
            zz[tid] = fadd2(fadd2(s0, s1), fadd2(s2, s3v));
        }
        __syncthreads();

        // ---------------- phase 3: epilogue, one thread per row --------------------
        if (tid < BATCH) {
            float z[6];
            #pragma unroll
            for (int p = 0; p < 3; ++p) {
                float2 v = unpack2(zz[tid * 3 + p]);
                z[2*p] = v.x; z[2*p + 1] = v.y;
            }
            float ss = 0.f;
            #pragma unroll
            for (int k = 0; k < 6; ++k) { z[k] = tanhf(z[k]); ss += z[k] * z[k]; }
            const float sc = s3_sh / fmaxf(sqrtf(ss), 1e-6f);   // 3*hs / ||z||

            float e[8]; float sum = 0.f;
            #pragma unroll
            for (int p = 0; p < 8; ++p) {
                float d = 0.f;
                #pragma unroll
                for (int k = 0; k < 6; ++k) d += z[k] * pn[p][k];
                e[p] = __expf(sc * d);
                sum += e[p];
            }
            const float rs  = 1.0f / sum;
            const int   row = r0 + tid;
            float4* op = reinterpret_cast<float4*>(out + (size_t)row * 8);
            op[0] = make_float4(e[0]*rs, e[1]*rs, e[2]*rs, e[3]*rs);
            op[1] = make_float4(e[4]*rs, e[5]*rs, e[6]*rs, e[7]*rs);
        }
        // next batch's phase-1 STS only reuses `part` (already consumed before the
        // second barrier); `zz` is rewritten only after the next barrier. Safe.
    }
}

extern "C" void kernel_launch(void* const* d_in, const int* in_sizes, int n_in,
                              void* d_out, int out_size) {
    const float* x     = (const float*)d_in[0];
    const float* W     = (const float*)d_in[1];
    const float* proto = (const float*)d_in[2];
    const float* hs    = (const float*)d_in[3];
    float* out = (float*)d_out;

    const int n_rows = in_sizes[0] / D_DIM;          // 32768
    const int grid   = n_rows / ROWS_PER_BLK;        // 512 (exact)
    q6_kernel<<<grid, THREADS>>>(x, W, proto, hs, out);
}